// round 17
// baseline (speedup 1.0000x reference)
#include <cuda_runtime.h>
#include <cuda_bf16.h>
#include <cuda_fp16.h>
#include <cstdint>

typedef unsigned long long u64;
typedef unsigned int       u32;

#define HWDIM 4096
#define CD    256
#define NB    4
#define NTILE 64
#define LOG2E 1.4426950408889634f

// ---------------- scratch (no allocations allowed) ----------------
__device__ __half        g_qh[(size_t)NB * HWDIM * 32];    // [b][n][o] fp16 Q (pre-scaled log2e)
__device__ __half        g_kh[(size_t)NB * HWDIM * 32];    // [b][n][o] fp16 K
__device__ __half        g_vh[(size_t)NB * CD * HWDIM];    // [b][c][n] fp16 V
__device__ __nv_bfloat16 g_oh[(size_t)NB * HWDIM * CD];    // [b][n][c] orig hi
__device__ __nv_bfloat16 g_ol[(size_t)NB * HWDIM * CD];    // [b][n][c] orig lo
__device__ __nv_bfloat16 g_wvh[CD * CD];                   // [c][k]
__device__ __nv_bfloat16 g_wvl[CD * CD];

// ---------------- helpers ----------------
__device__ __forceinline__ u32 saddr(const void* p) { return (u32)__cvta_generic_to_shared(p); }
__device__ __forceinline__ void cp16(u32 dst, const void* src) {
    asm volatile("cp.async.cg.shared.global [%0], [%1], 16;" :: "r"(dst), "l"(src));
}
__device__ __forceinline__ void cp_commit() { asm volatile("cp.async.commit_group;" ::: "memory"); }
__device__ __forceinline__ void cp_wait0()  { asm volatile("cp.async.wait_group 0;" ::: "memory"); }

__device__ __forceinline__ u32 bf2(float lo, float hi) {
    u32 r; asm("cvt.rn.bf16x2.f32 %0, %1, %2;" : "=r"(r) : "f"(hi), "f"(lo)); return r;
}
__device__ __forceinline__ u32 f162(float lo, float hi) {
    u32 r; asm("cvt.rn.f16x2.f32 %0, %1, %2;" : "=r"(r) : "f"(hi), "f"(lo)); return r;
}
__device__ __forceinline__ u64 pk64(u32 lo, u32 hi) {
    u64 r; asm("mov.b64 %0, {%1, %2};" : "=l"(r) : "r"(lo), "r"(hi)); return r;
}
__device__ __forceinline__ float lo16f(u32 h) { return __uint_as_float(h << 16); }
__device__ __forceinline__ float hi16f(u32 h) { return __uint_as_float(h & 0xFFFF0000u); }
__device__ __forceinline__ float f2lo(u64 v) { return __uint_as_float((u32)v); }
__device__ __forceinline__ float f2hi(u64 v) { return __uint_as_float((u32)(v >> 32)); }
__device__ __forceinline__ u64 ffma2(u64 a, u64 b, u64 c) {
    u64 d; asm("fma.rn.f32x2 %0, %1, %2, %3;" : "=l"(d) : "l"(a), "l"(b), "l"(c)); return d;
}
__device__ __forceinline__ u64 pack2(float lo, float hi) {
    u64 d; asm("mov.b64 %0, {%1, %2};" : "=l"(d) : "f"(lo), "f"(hi)); return d;
}
__device__ __forceinline__ float ex2f(float x) {
    float r; asm("ex2.approx.f32 %0, %1;" : "=f"(r) : "f"(x)); return r;
}
__device__ __forceinline__ void sts32(u32 a, u32 v) {
    asm volatile("st.shared.b32 [%0], %1;" :: "r"(a), "r"(v) : "memory");
}

#define LDSM4(r, a) \
    asm volatile("ldmatrix.sync.aligned.m8n8.x4.shared.b16 {%0,%1,%2,%3}, [%4];" \
        : "=r"((r)[0]), "=r"((r)[1]), "=r"((r)[2]), "=r"((r)[3]) : "r"(a))

#define MMA(d, a, b0_, b1_) \
    asm volatile("mma.sync.aligned.m16n8k16.row.col.f32.bf16.bf16.f32 " \
        "{%0,%1,%2,%3}, {%4,%5,%6,%7}, {%8,%9}, {%0,%1,%2,%3};" \
        : "+f"((d)[0]), "+f"((d)[1]), "+f"((d)[2]), "+f"((d)[3]) \
        : "r"((a)[0]), "r"((a)[1]), "r"((a)[2]), "r"((a)[3]), "r"(b0_), "r"(b1_))

#define MMAH(d, a, b0_, b1_) \
    asm volatile("mma.sync.aligned.m16n8k16.row.col.f32.f16.f16.f32 " \
        "{%0,%1,%2,%3}, {%4,%5,%6,%7}, {%8,%9}, {%0,%1,%2,%3};" \
        : "+f"((d)[0]), "+f"((d)[1]), "+f"((d)[2]), "+f"((d)[3]) \
        : "r"((a)[0]), "r"((a)[1]), "r"((a)[2]), "r"((a)[3]), "r"(b0_), "r"(b1_))

// =====================================================================
// Split+transpose: orig [b][c][n] fp32 -> g_oh/g_ol [b][n][c] bf16
// =====================================================================
__global__ __launch_bounds__(256) void split_orig_kernel(const float* __restrict__ orig)
{
    __shared__ float xs[64][65];
    const int tid = threadIdx.x;
    const int b = blockIdx.z;
    const int c0 = blockIdx.y * 64;
    const int n0 = blockIdx.x * 64;
    const float* ob = orig + ((size_t)b * CD + c0) * HWDIM + n0;
#pragma unroll
    for (int it = 0; it < 16; ++it) {
        int idx = tid + it * 256;
        int cc = idx >> 6, nn = idx & 63;
        xs[cc][nn] = ob[(size_t)cc * HWDIM + nn];
    }
    __syncthreads();
#pragma unroll
    for (int it = 0; it < 4; ++it) {
        int idx = tid + it * 256;
        int n = idx >> 4, c4 = (idx & 15) * 4;
        float y0 = xs[c4][n], y1 = xs[c4 + 1][n], y2 = xs[c4 + 2][n], y3 = xs[c4 + 3][n];
        u32 h01 = bf2(y0, y1), h23 = bf2(y2, y3);
        u32 l01 = bf2(y0 - lo16f(h01), y1 - hi16f(h01));
        u32 l23 = bf2(y2 - lo16f(h23), y3 - hi16f(h23));
        size_t off = ((size_t)b * HWDIM + n0 + n) * CD + c0 + c4;
        *(u64*)(g_oh + off) = pk64(h01, h23);
        *(u64*)(g_ol + off) = pk64(l01, l23);
    }
}

__global__ __launch_bounds__(256) void split_wv_kernel(const float* __restrict__ wv)
{
    int i = (blockIdx.x * 256 + threadIdx.x) * 4;
    float y0 = wv[i], y1 = wv[i + 1], y2 = wv[i + 2], y3 = wv[i + 3];
    u32 h01 = bf2(y0, y1), h23 = bf2(y2, y3);
    u32 l01 = bf2(y0 - lo16f(h01), y1 - hi16f(h01));
    u32 l23 = bf2(y2 - lo16f(h23), y3 - hi16f(h23));
    *(u64*)(g_wvh + i) = pk64(h01, h23);
    *(u64*)(g_wvl + i) = pk64(l01, l23);
}

// =====================================================================
// QK projection (fp32 FFMA2) -> fp16 Q/K [b][n][32]; Q scaled by log2e.
// =====================================================================
__global__ __launch_bounds__(256) void qk_proj_kernel(
    const float* __restrict__ x,
    const float* __restrict__ wq, const float* __restrict__ bq,
    const float* __restrict__ wk, const float* __restrict__ bk)
{
    __shared__ float xs[64][65];
    __shared__ float ws[64][66];
    const int tid = threadIdx.x;
    const int b = blockIdx.y;
    const int n0 = blockIdx.x * 64;
    const int tx = tid & 15, ty = tid >> 4;

    u64 acc[4][2];
#pragma unroll
    for (int i = 0; i < 4; ++i) { acc[i][0] = 0ull; acc[i][1] = 0ull; }

    const float* xb = x + (size_t)b * CD * HWDIM;

    for (int c0 = 0; c0 < CD; c0 += 64) {
        __syncthreads();
#pragma unroll
        for (int it = 0; it < 16; ++it) {
            int idx = tid + it * 256;
            int cc = idx >> 6, nn = idx & 63;
            xs[cc][nn] = xb[(size_t)(c0 + cc) * HWDIM + n0 + nn];
        }
#pragma unroll
        for (int it = 0; it < 16; ++it) {
            int idx = tid + it * 256;
            int o = idx >> 6, cc = idx & 63;
            ws[cc][o] = (o < 32) ? wq[o * CD + c0 + cc] : wk[(o - 32) * CD + c0 + cc];
        }
        __syncthreads();
#pragma unroll 8
        for (int kk = 0; kk < 64; ++kk) {
            u64 a0 = *(const u64*)&ws[kk][ty * 4];
            u64 a1 = *(const u64*)&ws[kk][ty * 4 + 2];
#pragma unroll
            for (int i = 0; i < 4; ++i) {
                float bv2 = xs[kk][tx * 4 + i];
                u64 bd = pack2(bv2, bv2);
                acc[i][0] = ffma2(a0, bd, acc[i][0]);
                acc[i][1] = ffma2(a1, bd, acc[i][1]);
            }
        }
    }
    const int og = ty * 4;
    float bb0, bb1, bb2, bb3;
    if (ty < 8) { bb0 = bq[og]; bb1 = bq[og + 1]; bb2 = bq[og + 2]; bb3 = bq[og + 3]; }
    else        { bb0 = bk[og - 32]; bb1 = bk[og - 31]; bb2 = bk[og - 30]; bb3 = bk[og - 29]; }
    __half* arr = (ty < 8) ? g_qh : g_kh;
    const int ol = (ty < 8) ? og : og - 32;
    const float sc = (ty < 8) ? LOG2E : 1.0f;   // fold log2e into Q -> attn uses ex2
#pragma unroll
    for (int i = 0; i < 4; ++i) {
        int n = n0 + tx * 4 + i;
        float f0 = (f2lo(acc[i][0]) + bb0) * sc;
        float f1 = (f2hi(acc[i][0]) + bb1) * sc;
        float f2 = (f2lo(acc[i][1]) + bb2) * sc;
        float f3 = (f2hi(acc[i][1]) + bb3) * sc;
        *(u64*)(arr + ((size_t)b * HWDIM + n) * 32 + ol) = pk64(f162(f0, f1), f162(f2, f3));
    }
}

// =====================================================================
// V projection via mma.sync bf16 (3-term) -> fp16 g_vh[b][c][n]
// =====================================================================
#define VSWH 0u
#define VSWL 33792u
#define VSB  67584u
#define VSBB 73728u
#define VSXL 36864u
#define VPROJ_SMEM 215040

__global__ __launch_bounds__(256, 1) void v_proj_mma_kernel(const float* __restrict__ bv)
{
    extern __shared__ char smem_raw[];
    const u32 sb = saddr(smem_raw);
    const int tid = threadIdx.x;
    const int lane = tid & 31;
    const int warp = tid >> 5;
    const int b = blockIdx.z;
    const int ctile = blockIdx.y * 64;
    const int n0 = blockIdx.x * 256;
    const int rm = warp >> 1;
    const int nh = warp & 1;

    const __nv_bfloat16* xh = g_oh + (size_t)b * HWDIM * CD;
    const __nv_bfloat16* xl = g_ol + (size_t)b * HWDIM * CD;

#pragma unroll
    for (int it = 0; it < 8; ++it) {
        int idx = tid + it * 256;
        int r = idx >> 5, ch = idx & 31;
        cp16(sb + VSWH + (u32)(r * 528 + ch * 16), g_wvh + (ctile + r) * CD + ch * 8);
        cp16(sb + VSWL + (u32)(r * 528 + ch * 16), g_wvl + (ctile + r) * CD + ch * 8);
    }
#pragma unroll
    for (int it = 0; it < 8; ++it) {
        int idx = tid + it * 256;
        int r = idx >> 3, ch = idx & 7;
        u32 doff = (u32)(r * 144 + ch * 16);
        size_t soff = (size_t)(n0 + r) * CD + ch * 8;
        cp16(sb + VSB + doff, xh + soff);
        cp16(sb + VSB + VSXL + doff, xl + soff);
    }
    cp_commit();

    float o[16][4];
#pragma unroll
    for (int i = 0; i < 16; ++i) { o[i][0] = 0.f; o[i][1] = 0.f; o[i][2] = 0.f; o[i][3] = 0.f; }

    for (int ks = 0; ks < 4; ++ks) {
        const int buf = ks & 1;
        cp_wait0();
        __syncthreads();
        if (ks < 3) {
#pragma unroll
            for (int it = 0; it < 8; ++it) {
                int idx = tid + it * 256;
                int r = idx >> 3, ch = idx & 7;
                u32 doff = (u32)((buf ^ 1) * VSBB + r * 144 + ch * 16);
                size_t soff = (size_t)(n0 + r) * CD + (ks + 1) * 64 + ch * 8;
                cp16(sb + VSB + doff, xh + soff);
                cp16(sb + VSB + VSXL + doff, xl + soff);
            }
            cp_commit();
        }

        u32 wh[4][4], wl[4][4];
        {
            u32 abase = sb + (u32)((rm * 16 + (lane & 15)) * 528 + ks * 128 + (lane >> 4) * 16);
#pragma unroll
            for (int j = 0; j < 4; ++j) {
                LDSM4(wh[j], abase + VSWH + (u32)(j * 32));
                LDSM4(wl[j], abase + VSWL + (u32)(j * 32));
            }
        }
        const u32 vbb = sb + VSB + (u32)buf * VSBB + (u32)((nh * 128 + (lane & 7)) * 144 + (lane >> 3) * 16);
#pragma unroll
        for (int nt = 0; nt < 16; ++nt) {
            u32 xh0[4], xh1[4], xl0[4], xl1[4];
            u32 rb = vbb + (u32)(nt * 1152);
            LDSM4(xh0, rb);
            LDSM4(xh1, rb + 64);
            LDSM4(xl0, rb + VSXL);
            LDSM4(xl1, rb + VSXL + 64);
            MMA(o[nt], wh[0], xh0[0], xh0[1]);
            MMA(o[nt], wh[1], xh0[2], xh0[3]);
            MMA(o[nt], wh[2], xh1[0], xh1[1]);
            MMA(o[nt], wh[3], xh1[2], xh1[3]);
            MMA(o[nt], wh[0], xl0[0], xl0[1]);
            MMA(o[nt], wh[1], xl0[2], xl0[3]);
            MMA(o[nt], wh[2], xl1[0], xl1[1]);
            MMA(o[nt], wh[3], xl1[2], xl1[3]);
            MMA(o[nt], wl[0], xh0[0], xh0[1]);
            MMA(o[nt], wl[1], xh0[2], xh0[3]);
            MMA(o[nt], wl[2], xh1[0], xh1[1]);
            MMA(o[nt], wl[3], xh1[2], xh1[3]);
        }
    }

    const int r0 = rm * 16 + (lane >> 2);
    const float b0 = bv[ctile + r0];
    const float b1 = bv[ctile + r0 + 8];
    __half* v0 = g_vh + ((size_t)b * CD + ctile + r0) * HWDIM + n0 + nh * 128 + 2 * (lane & 3);
    __half* v1 = v0 + (size_t)8 * HWDIM;
#pragma unroll
    for (int nt = 0; nt < 16; ++nt) {
        *(u32*)(v0 + nt * 8) = f162(o[nt][0] + b0, o[nt][1] + b0);
        *(u32*)(v1 + nt * 8) = f162(o[nt][2] + b1, o[nt][3] + b1);
    }
}

// =====================================================================
// Flash attention, fp16 single-term S (Q,K fp16; products exact in f32):
// MMA1 roles: warp = (q-block, j-half): S[16q x 32j], 8 fp16 MMAs + 16 ex2.
// Row max via smem (exact online softmax), P fp16 in smem.
// MMA2 roles: warp = (q-block, c-half): O += P(ldsm) x V, 64 fp16 MMAs.
// 256 threads (8 warps); CTA = 64 q; grid (64, 4); 2 CTAs/SM.
// =====================================================================
#define SQ    0u
#define SK    5120u         // 2 bufs x 64 x 80
#define SKB   5120u
#define SV    15360u        // 2 bufs x 256 x 144
#define SVB   36864u
#define SP    89088u        // 64 x 144
#define MXOFF 98304u
#define LSOFF 98816u
#define ATTN_SMEM 99328

__device__ __forceinline__ void load_kv_tile(u32 sb, int buf, int j0, int tid,
    const __half* kg, const __half* vh)
{
    // K tile: 64 j x 32 o fp16 (64B/row, pitch 80)
    {
        int r = tid >> 2, c = tid & 3;
        cp16(sb + SK + (u32)buf * SKB + (u32)(r * 80 + c * 16),
             kg + (size_t)(j0 + r) * 32 + c * 8);
    }
    u32 vb = sb + SV + (u32)buf * SVB;
#pragma unroll
    for (int i = 0; i < 8; ++i) {
        int idx = tid + i * 256;
        int r = idx >> 3, c = idx & 7;
        cp16(vb + (u32)(r * 144 + c * 16), vh + (size_t)r * HWDIM + j0 + c * 8);
    }
}

__global__ __launch_bounds__(256, 2) void attn_kernel(
    const float* __restrict__ inp,
    const float* __restrict__ gamma_p,
    float* __restrict__ out)
{
    extern __shared__ char smem_raw[];
    const u32 sb = saddr(smem_raw);
    const int tid = threadIdx.x;
    const int lane = tid & 31;
    const int warp = tid >> 5;
    const int b = blockIdx.y;
    const int n0 = blockIdx.x * 64;
    const int qb = warp >> 1;
    const int q0 = qb * 16;
    const int jh = warp & 1;          // j-half for MMA1/softmax
    const int c0 = jh * 128;          // c-half for MMA2

    const __half* qg = g_qh + ((size_t)b * HWDIM + n0) * 32;
    const __half* kg = g_kh + (size_t)b * HWDIM * 32;
    const __half* vh = g_vh + (size_t)b * CD * HWDIM;

    // Q tile: 64 q x 32 o fp16, pitch 80
    {
        int r = tid >> 2, c = tid & 3;
        cp16(sb + SQ + (u32)(r * 80 + c * 16), qg + (size_t)r * 32 + c * 8);
    }
    load_kv_tile(sb, 0, 0, tid, kg, vh);
    cp_commit();
    cp_wait0();
    __syncthreads();

    u32 qh[2][4];
    {
        u32 base = sb + SQ + (u32)((q0 + (lane & 15)) * 80 + (lane >> 4) * 16);
        LDSM4(qh[0], base);
        LDSM4(qh[1], base + 32);
    }

    float o[16][4];
#pragma unroll
    for (int i = 0; i < 16; ++i) { o[i][0] = 0.f; o[i][1] = 0.f; o[i][2] = 0.f; o[i][3] = 0.f; }
    float lr0 = 0.f, lr1 = 0.f;
    float m0 = -1e30f, m1 = -1e30f;

    float* mxs = (float*)(smem_raw + MXOFF);
    const int rr = lane >> 2;

    for (int t = 0; t < NTILE; ++t) {
        const int buf = t & 1;
        if (t) cp_wait0();
        __syncthreads();                 // KV(t) ready; P/mx consumed by all warps
        if (t + 1 < NTILE) { load_kv_tile(sb, buf ^ 1, (t + 1) * 64, tid, kg, vh); cp_commit(); }

        // ---- MMA1 (fp16 single-term) own (q-block, j-half): S[16 x 32] ----
        float st[4][4];
        const u32 kbase = sb + SK + (u32)buf * SKB + (u32)(jh * 2560)
                        + (u32)((lane & 7) * 80 + (lane >> 3) * 16);
#pragma unroll
        for (int n4 = 0; n4 < 4; ++n4) {
            u32 bh[4];
            LDSM4(bh, kbase + (u32)(n4 * 640));
            st[n4][0] = 0.f; st[n4][1] = 0.f; st[n4][2] = 0.f; st[n4][3] = 0.f;
            MMAH(st[n4], qh[0], bh[0], bh[1]);
            MMAH(st[n4], qh[1], bh[2], bh[3]);
        }
        // ---- warp-local row max over own 32 j, publish to smem ----
        float mx0 = fmaxf(fmaxf(st[0][0], st[0][1]), fmaxf(st[1][0], st[1][1]));
        mx0 = fmaxf(mx0, fmaxf(fmaxf(st[2][0], st[2][1]), fmaxf(st[3][0], st[3][1])));
        float mx1 = fmaxf(fmaxf(st[0][2], st[0][3]), fmaxf(st[1][2], st[1][3]));
        mx1 = fmaxf(mx1, fmaxf(fmaxf(st[2][2], st[2][3]), fmaxf(st[3][2], st[3][3])));
        mx0 = fmaxf(mx0, __shfl_xor_sync(0xffffffffu, mx0, 1));
        mx0 = fmaxf(mx0, __shfl_xor_sync(0xffffffffu, mx0, 2));
        mx1 = fmaxf(mx1, __shfl_xor_sync(0xffffffffu, mx1, 1));
        mx1 = fmaxf(mx1, __shfl_xor_sync(0xffffffffu, mx1, 2));
        if ((lane & 3) == 0) {
            mxs[jh * 64 + q0 + rr]     = mx0;
            mxs[jh * 64 + q0 + 8 + rr] = mx1;
        }
        __syncthreads();                 // maxima visible
        float mA = fmaxf(m0, fmaxf(mxs[q0 + rr],     mxs[64 + q0 + rr]));
        float mB = fmaxf(m1, fmaxf(mxs[q0 + 8 + rr], mxs[64 + q0 + 8 + rr]));
        if (__any_sync(0xffffffffu, (mA > m0) || (mB > m1))) {
            float a0 = ex2f(m0 - mA), a1 = ex2f(m1 - mB);
            lr0 *= a0; lr1 *= a1;
#pragma unroll
            for (int i = 0; i < 16; ++i) {
                o[i][0] *= a0; o[i][1] *= a0; o[i][2] *= a1; o[i][3] *= a1;
            }
        }
        m0 = mA; m1 = mB;
        // ---- exp + store P (fp16) to smem ----
        const u32 prow = sb + SP + (u32)((q0 + rr) * 144 + (jh * 32 + 2 * (lane & 3)) * 2);
#pragma unroll
        for (int n4 = 0; n4 < 4; ++n4) {
            float p0 = ex2f(st[n4][0] - m0);
            float p1 = ex2f(st[n4][1] - m0);
            float p2 = ex2f(st[n4][2] - m1);
            float p3 = ex2f(st[n4][3] - m1);
            lr0 += p0 + p1;
            lr1 += p2 + p3;
            sts32(prow + (u32)(n4 * 16),              f162(p0, p1));
            sts32(prow + (u32)(8 * 144 + n4 * 16),    f162(p2, p3));
        }
        __syncthreads();                 // P tile complete

        // ---- MMA2 (fp16): warp = (q-block, c-half); P via ldmatrix ----
        u32 pa[4][4];
        {
            const u32 pbase = sb + SP + (u32)((q0 + (lane & 15)) * 144 + (lane >> 4) * 16);
#pragma unroll
            for (int ks = 0; ks < 4; ++ks) LDSM4(pa[ks], pbase + (u32)(ks * 32));
        }
        const u32 vbb = sb + SV + (u32)buf * SVB + (u32)((c0 + (lane & 7)) * 144 + (lane >> 3) * 16);
#pragma unroll
        for (int nt = 0; nt < 16; ++nt) {
            u32 v0[4], v1[4];
            u32 rb = vbb + (u32)(nt * 1152);
            LDSM4(v0, rb);
            LDSM4(v1, rb + 64);
            MMAH(o[nt], pa[0], v0[0], v0[1]);
            MMAH(o[nt], pa[1], v0[2], v0[3]);
            MMAH(o[nt], pa[2], v1[0], v1[1]);
            MMAH(o[nt], pa[3], v1[2], v1[3]);
        }
    }

    // ---- epilogue ----
    lr0 += __shfl_xor_sync(0xffffffffu, lr0, 1);
    lr0 += __shfl_xor_sync(0xffffffffu, lr0, 2);
    lr1 += __shfl_xor_sync(0xffffffffu, lr1, 1);
    lr1 += __shfl_xor_sync(0xffffffffu, lr1, 2);
    float* ls = (float*)(smem_raw + LSOFF);
    if ((lane & 3) == 0) {
        ls[jh * 64 + q0 + rr]     = lr0;    // per-(j-half) partial l
        ls[jh * 64 + q0 + 8 + rr] = lr1;
    }
    __syncthreads();

    float* Os = (float*)smem_raw;
    if (tid < 64) ls[tid] = gamma_p[0] / (ls[tid] + ls[tid + 64]);
#pragma unroll
    for (int nt = 0; nt < 16; ++nt) {
        int cc = c0 + 8 * nt + 2 * (lane & 3);
        int qq = q0 + rr;
        Os[cc * 68 + qq]            = o[nt][0];
        Os[(cc + 1) * 68 + qq]      = o[nt][1];
        Os[cc * 68 + qq + 8]        = o[nt][2];
        Os[(cc + 1) * 68 + qq + 8]  = o[nt][3];
    }
    __syncthreads();

    const float* ib = inp + (size_t)b * CD * HWDIM + n0;
    float* ob = out + (size_t)b * CD * HWDIM + n0;
#pragma unroll 4
    for (int it = 0; it < 64; ++it) {
        int idx = tid + it * 256;
        int c = idx >> 6, q = idx & 63;
        ob[(size_t)c * HWDIM + q] = Os[c * 68 + q] * ls[q] + ib[(size_t)c * HWDIM + q];
    }
}

// =====================================================================
extern "C" void kernel_launch(void* const* d_in, const int* in_sizes, int n_in,
                              void* d_out, int out_size)
{
    (void)in_sizes; (void)n_in; (void)out_size;
    const float* input    = (const float*)d_in[0];
    const float* original = (const float*)d_in[1];
    const float* wq    = (const float*)d_in[2];
    const float* bq    = (const float*)d_in[3];
    const float* wk    = (const float*)d_in[4];
    const float* bk    = (const float*)d_in[5];
    const float* wv    = (const float*)d_in[6];
    const float* bv    = (const float*)d_in[7];
    const float* gamma = (const float*)d_in[8];
    float* out = (float*)d_out;

    cudaFuncSetAttribute(attn_kernel, cudaFuncAttributeMaxDynamicSharedMemorySize, ATTN_SMEM);
    cudaFuncSetAttribute(v_proj_mma_kernel, cudaFuncAttributeMaxDynamicSharedMemorySize, VPROJ_SMEM);

    split_orig_kernel<<<dim3(HWDIM / 64, CD / 64, NB), 256>>>(original);
    split_wv_kernel<<<64, 256>>>(wv);
    qk_proj_kernel<<<dim3(HWDIM / 64, NB), 256>>>(input, wq, bq, wk, bk);
    v_proj_mma_kernel<<<dim3(HWDIM / 256, CD / 64, NB), 256, VPROJ_SMEM>>>(bv);
    attn_kernel<<<dim3(HWDIM / 64, NB), 256, ATTN_SMEM>>>(input, gamma, out);
}